// round 15
// baseline (speedup 1.0000x reference)
#include <cuda_runtime.h>
#include <cuda_bf16.h>
#include <cstdint>
#include <math.h>

#define BATCH 8
#define TQ    2048
#define TK    2048
#define HD    1024

#if defined(__CUDA_ARCH_FEAT_SM103_ALL) || defined(__CUDA_ARCH_FEAT_SM100_ALL)
#define HAS_TCGEN05 1
#else
#define HAS_TCGEN05 0
#endif

// ---------------------------------------------------------------------------
// Device scratch. GEMM operands stored TILED: contiguous 16KB blocks that are
// the exact SW128 smem image of a 128-row x 64-col bf16 sub-tile.
//   Q  : [B][TQ/128=16][HD/64=16] blocks
//   K  : [B][TK/128=16][HD/64=16] blocks
//   KT : [B][HD/128= 8][TK/64=32] blocks
//   P  : [B][TQ/128=16][TK/64=32] blocks
// ---------------------------------------------------------------------------
__device__ float         g_E   [(size_t)BATCH * TQ * TK];
__device__ __nv_bfloat16 g_Qhi [(size_t)BATCH * TQ * HD];
__device__ __nv_bfloat16 g_Qlo [(size_t)BATCH * TQ * HD];
__device__ __nv_bfloat16 g_Khi [(size_t)BATCH * TK * HD];
__device__ __nv_bfloat16 g_Klo [(size_t)BATCH * TK * HD];
__device__ __nv_bfloat16 g_KThi[(size_t)BATCH * HD * TK];
__device__ __nv_bfloat16 g_KTlo[(size_t)BATCH * HD * TK];
__device__ __nv_bfloat16 g_Phi [(size_t)BATCH * TQ * TK];
__device__ __nv_bfloat16 g_Plo [(size_t)BATCH * TQ * TK];

// ---------------------------------------------------------------------------
// Common helpers
// ---------------------------------------------------------------------------
__device__ __forceinline__ uint32_t smem_u32(const void* p) {
    uint32_t a;
    asm("{ .reg .u64 t; cvta.to.shared.u64 t, %1; cvt.u32.u64 %0, t; }" : "=r"(a) : "l"(p));
    return a;
}

__device__ __forceinline__ void split_bf16(float x, __nv_bfloat16& h, __nv_bfloat16& l) {
    h = __float2bfloat16(x);
    l = __float2bfloat16(x - __bfloat162float(h));
}

__device__ __forceinline__ uint32_t pack2(__nv_bfloat16 a, __nv_bfloat16 b) {
    __nv_bfloat162 t(a, b);
    return *(uint32_t*)&t;
}

__device__ __forceinline__ uint32_t sw128(uint32_t off) {
    return off ^ ((off >> 3) & 0x70);
}

#define CP_ASYNC16(dst, src) \
    asm volatile("cp.async.cg.shared.global [%0], [%1], 16;" :: "r"(dst), "l"(src) : "memory")
#define CP_COMMIT()  asm volatile("cp.async.commit_group;" ::: "memory")
#define CP_WAITG(n)  asm volatile("cp.async.wait_group %0;" :: "n"(n) : "memory")

#define CLUSTER_ARRIVE() asm volatile("barrier.cluster.arrive.aligned;" ::: "memory")
#define CLUSTER_WAIT()   asm volatile("barrier.cluster.wait.aligned;"   ::: "memory")

// ---------------------------------------------------------------------------
// tcgen05 helpers (only in the sm_103a feature pass)
// ---------------------------------------------------------------------------
#if HAS_TCGEN05
#define MBARRIER_INIT(addr, cnt) \
    asm volatile("mbarrier.init.shared.b64 [%0], %1;" :: "r"((uint32_t)(addr)), "r"((uint32_t)(cnt)) : "memory")

#define MBARRIER_WAIT_PARITY(addr, parity) do {                                              \
    uint32_t _m = (uint32_t)(addr); uint32_t _p = (uint32_t)(parity); uint32_t _d;            \
    asm volatile("{\n\t.reg .pred p;\n\t"                                                     \
        "mbarrier.try_wait.parity.acquire.cta.shared::cta.b64 p, [%1], %2;\n\t"               \
        "selp.b32 %0, 1, 0, p;\n\t}" : "=r"(_d) : "r"(_m), "r"(_p) : "memory");               \
    if (!_d) {                                                                                \
        asm volatile("{\n\t.reg .pred P1;\n\t"                                                \
            "WL_%=:\n\t"                                                                      \
            "mbarrier.try_wait.parity.acquire.cta.shared::cta.b64 P1, [%0], %1, 0x989680;\n\t"\
            "@P1 bra.uni WD_%=;\n\t"                                                          \
            "bra.uni WL_%=;\n\t"                                                              \
            "WD_%=:\n\t}" :: "r"(_m), "r"(_p) : "memory");                                    \
    }                                                                                         \
} while (0)

// arrive on the same-offset mbarrier in cluster CTA `rank` (R8-proven)
#define MBARRIER_ARRIVE_CLUSTER(local_addr, rank) \
    asm volatile("{\n\t.reg .b32 r;\n\t" \
        "mapa.shared::cluster.u32 r, %0, %1;\n\t" \
        "mbarrier.arrive.release.cluster.shared::cluster.b64 _, [r];\n\t}" \
        :: "r"((uint32_t)(local_addr)), "r"((uint32_t)(rank)) : "memory")

#define TCGEN05_ALLOC_CG2(smem_addr, ncols) \
    asm volatile("tcgen05.alloc.cta_group::2.sync.aligned.shared::cta.b32 [%0], %1;" \
                 :: "r"((uint32_t)(smem_addr)), "r"((uint32_t)(ncols)) : "memory")
#define TCGEN05_DEALLOC_CG2(tmem, ncols) \
    asm volatile("tcgen05.dealloc.cta_group::2.sync.aligned.b32 %0, %1;" :: "r"(tmem), "r"((uint32_t)(ncols)))
#define TCGEN05_RELINQUISH_CG2() \
    asm volatile("tcgen05.relinquish_alloc_permit.cta_group::2.sync.aligned;")
#define TCGEN05_COMMIT_MC_CG2(mbar) \
    asm volatile("tcgen05.commit.cta_group::2.mbarrier::arrive::one.shared::cluster.multicast::cluster.b64 [%0], %1;" \
                 :: "r"((uint32_t)(mbar)), "h"((uint16_t)0x3) : "memory")
#define TCGEN05_FENCE_AFTER()  asm volatile("tcgen05.fence::after_thread_sync;"  ::: "memory")
#define TCGEN05_FENCE_BEFORE() asm volatile("tcgen05.fence::before_thread_sync;" ::: "memory")
#define TCGEN05_WAIT_LD()      asm volatile("tcgen05.wait::ld.sync.aligned;"     ::: "memory")
#define FENCE_PROXY_ASYNC()    asm volatile("fence.proxy.async.shared::cta;"     ::: "memory")

#define TCGEN05_LD_32X32B_X32(r, tmem_addr) \
    asm volatile( \
        "tcgen05.ld.sync.aligned.32x32b.x32.b32 " \
        "{%0, %1, %2, %3, %4, %5, %6, %7, " \
        " %8, %9, %10, %11, %12, %13, %14, %15, " \
        " %16, %17, %18, %19, %20, %21, %22, %23, " \
        " %24, %25, %26, %27, %28, %29, %30, %31}, [%32];" \
        : "=r"((r)[0]),  "=r"((r)[1]),  "=r"((r)[2]),  "=r"((r)[3]), \
          "=r"((r)[4]),  "=r"((r)[5]),  "=r"((r)[6]),  "=r"((r)[7]), \
          "=r"((r)[8]),  "=r"((r)[9]),  "=r"((r)[10]), "=r"((r)[11]), \
          "=r"((r)[12]), "=r"((r)[13]), "=r"((r)[14]), "=r"((r)[15]), \
          "=r"((r)[16]), "=r"((r)[17]), "=r"((r)[18]), "=r"((r)[19]), \
          "=r"((r)[20]), "=r"((r)[21]), "=r"((r)[22]), "=r"((r)[23]), \
          "=r"((r)[24]), "=r"((r)[25]), "=r"((r)[26]), "=r"((r)[27]), \
          "=r"((r)[28]), "=r"((r)[29]), "=r"((r)[30]), "=r"((r)[31]) \
        : "r"(tmem_addr))

__device__ __forceinline__ void mma_f16_ss_cg2(uint32_t d, uint64_t ad, uint64_t bd,
                                               uint32_t idesc, bool acc) {
    uint32_t en = acc ? 1u : 0u;
    asm volatile(
        "{\n\t.reg .pred p;\n\tsetp.ne.u32 p, %5, 0;\n\t"
        "tcgen05.mma.cta_group::2.kind::f16 [%0], %1, %2, %3, "
        "{%4, %4, %4, %4, %4, %4, %4, %4}, p;\n\t}"
        :: "r"(d), "l"(ad), "l"(bd), "r"(idesc), "r"(0u), "r"(en) : "memory");
}

__device__ __forceinline__ uint64_t make_desc(uint32_t addr) {
    const uint64_t base = (2ULL << 61) | (1ULL << 46) | (64ULL << 32) | (1ULL << 16);
    return base | ((uint64_t)(addr >> 4) & 0x3FFF);
}
// dtype=F32, a/b=BF16, N=256 (32<<17), M=256 (16<<24) for cta_group::2
#define MMA_IDESC_CG2 0x10400490u
#endif  // HAS_TCGEN05

// ---------------------------------------------------------------------------
// GEMM: C[M,N] = (Ahi+Alo)[M,Kt] * (Bhi+Blo)[N,Kt]^T, fp32 out, TILED operands.
// 2-CTA cluster tile: M=256 (128/CTA) x N=256 (B split 128/CTA). K chunk 64.
// SINGLE 64KB smem stage, serial per-CTA loop; latency hidden by a SECOND
// co-resident CTA (launch_bounds(256,2), smem 66.5KB -> 2 CTAs/SM, two
// independent clusters per SM pair interleave loads and MMAs).
// Grid: x = (N/256)*2, y = M/256, z = batch.
// ---------------------------------------------------------------------------
#define SM_TMEMPTR  0
#define SM_READY    16
#define SM_DONE     24
#define SM_BUF      1024
#define STAGE_BYTES 65536          // Ahi | Alo | Bhi | Blo, 16KB each
#define GEMM_SMEM   (SM_BUF + STAGE_BYTES)

__global__ void __launch_bounds__(256, 2) __cluster_dims__(2, 1, 1)
gemm_split_kernel(const __nv_bfloat16* __restrict__ Ahi, const __nv_bfloat16* __restrict__ Alo,
                  const __nv_bfloat16* __restrict__ Bhi, const __nv_bfloat16* __restrict__ Blo,
                  float* __restrict__ C, int M, int N, int Ktot)
{
#if HAS_TCGEN05
    extern __shared__ char smem[];
    const uint32_t sb = smem_u32(smem);
    const int tid = threadIdx.x;
    const int wid = tid >> 5, lid = tid & 31;
    const int rank = (int)(blockIdx.x & 1);
    const int n0 = (int)(blockIdx.x >> 1) * 256;
    const int m0 = (int)blockIdx.y * 256;

    const int mt128 = M >> 7, nt128 = N >> 7;
    const int nch = Ktot >> 6;
    const int atile = (int)blockIdx.y * 2 + rank;
    const int btile = (int)(blockIdx.x >> 1) * 2 + rank;
    const size_t ablk0 = ((size_t)blockIdx.z * mt128 + atile) * nch;
    const size_t bblk0 = ((size_t)blockIdx.z * nt128 + btile) * nch;

    const char* srcs[4] = {
        (const char*)(Ahi + ablk0 * 8192),
        (const char*)(Alo + ablk0 * 8192),
        (const char*)(Bhi + bblk0 * 8192),
        (const char*)(Blo + bblk0 * 8192),
    };

    if (wid == 0) TCGEN05_ALLOC_CG2(sb + SM_TMEMPTR, 256);
    if (tid == 0) {
        MBARRIER_INIT(sb + SM_READY, 2);   // tid0 of each CTA
        MBARRIER_INIT(sb + SM_DONE, 1);    // multicast commit per chunk
    }
    __syncthreads();
    uint32_t tmem;
    asm volatile("ld.shared.b32 %0, [%1];" : "=r"(tmem) : "r"(sb + SM_TMEMPTR));

    CLUSTER_ARRIVE(); CLUSTER_WAIT();

#pragma unroll 1
    for (int c = 0; c < nch; c++) {
        // buffer reuse gate: chunk c-1's MMAs must have retired.
        // All threads participate every iteration -> sequential phases from 0,
        // no parity aliasing, no cold waiters.
        if (c > 0) MBARRIER_WAIT_PARITY(sb + SM_DONE, (c - 1) & 1);

        // load this CTA's 64KB chunk: 16 cp.async per thread
        {
            const size_t coff = (size_t)c * 16384;
#pragma unroll
            for (int s = 0; s < 4; s++) {
                const char* gs = srcs[s] + coff;
                const uint32_t ds = sb + SM_BUF + s * 16384;
#pragma unroll
                for (int j = 0; j < 4; j++) {
                    const uint32_t o = (uint32_t)(tid + j * 256) * 16;
                    CP_ASYNC16(ds + o, gs + o);
                }
            }
            CP_COMMIT();
        }
        CP_WAITG(0);
        __syncthreads();
        FENCE_PROXY_ASYNC();
        if (tid == 0) MBARRIER_ARRIVE_CLUSTER(sb + SM_READY, 0);

        if (rank == 0 && tid == 0) {
            MBARRIER_WAIT_PARITY(sb + SM_READY, c & 1);
            const uint64_t dAh = make_desc(sb + SM_BUF + 0);
            const uint64_t dAl = make_desc(sb + SM_BUF + 16384);
            const uint64_t dBh = make_desc(sb + SM_BUF + 32768);
            const uint64_t dBl = make_desc(sb + SM_BUF + 49152);
            const bool first = (c == 0);
#pragma unroll
            for (int s = 0; s < 4; s++)
                mma_f16_ss_cg2(tmem, dAh + s * 2, dBh + s * 2, MMA_IDESC_CG2, !(first && s == 0));
#pragma unroll
            for (int s = 0; s < 4; s++)
                mma_f16_ss_cg2(tmem, dAh + s * 2, dBl + s * 2, MMA_IDESC_CG2, true);
#pragma unroll
            for (int s = 0; s < 4; s++)
                mma_f16_ss_cg2(tmem, dAl + s * 2, dBh + s * 2, MMA_IDESC_CG2, true);
            TCGEN05_COMMIT_MC_CG2(sb + SM_DONE);
        }
    }

    // final: all threads waited DONE phases 0..nch-2 in-loop; wait last phase
    MBARRIER_WAIT_PARITY(sb + SM_DONE, (nch - 1) & 1);
    TCGEN05_FENCE_AFTER();

    // epilogue: each CTA reads its own 128x256 from TMEM
    {
        const int sub = wid & 3, half = wid >> 2;
        const int row = sub * 32 + lid;
        float* crow = C + (size_t)blockIdx.z * M * N
                      + (size_t)(m0 + rank * 128 + row) * N + n0 + half * 128;
#pragma unroll
        for (int g = 0; g < 4; g++) {
            uint32_t regs[32];
            TCGEN05_LD_32X32B_X32(regs, tmem + half * 128 + g * 32);
            TCGEN05_WAIT_LD();
#pragma unroll
            for (int q = 0; q < 8; q++) {
                float4 f;
                f.x = __uint_as_float(regs[q * 4 + 0]);
                f.y = __uint_as_float(regs[q * 4 + 1]);
                f.z = __uint_as_float(regs[q * 4 + 2]);
                f.w = __uint_as_float(regs[q * 4 + 3]);
                *(float4*)(crow + g * 32 + q * 4) = f;
            }
        }
    }
    TCGEN05_FENCE_BEFORE();
    __syncthreads();
    if (wid == 0) {
        TCGEN05_RELINQUISH_CG2();
        TCGEN05_DEALLOC_CG2(tmem, 256);
    }
    CLUSTER_ARRIVE(); CLUSTER_WAIT();
#else
    // =============== non-feature fallback: naive tiled GEMM ===============
    const int tid = threadIdx.x;
    const int rank = (int)(blockIdx.x & 1);
    const int m0 = (int)blockIdx.y * 256 + rank * 128;
    const int n0 = (int)(blockIdx.x >> 1) * 256;
    const int mt128 = M >> 7, nt128 = N >> 7;
    const int nch = Ktot >> 6;

    auto ld2 = [&](const __nv_bfloat16* hi, const __nv_bfloat16* lo,
                   size_t tblk, int r, int e) -> float {
        const size_t blk = tblk * nch + (e >> 6);
        const uint32_t off = sw128((uint32_t)((r & 127) * 128 + (e & 63) * 2));
        float h = __bfloat162float(*(const __nv_bfloat16*)((const char*)hi + blk * 16384 + off));
        float l = __bfloat162float(*(const __nv_bfloat16*)((const char*)lo + blk * 16384 + off));
        return h + l;
    };

    const size_t atblk = (size_t)blockIdx.z * mt128 + (m0 >> 7);
    for (int idx = tid; idx < 128 * 256; idx += 256) {
        const int r = idx >> 8;
        const int j = idx & 255;
        const int gcol = n0 + j;
        const size_t btblk = (size_t)blockIdx.z * nt128 + (gcol >> 7);
        float acc = 0.0f;
        for (int e = 0; e < Ktot; e++)
            acc += ld2(Ahi, Alo, atblk, r, e) * ld2(Bhi, Blo, btblk, gcol & 127, e);
        C[(size_t)blockIdx.z * M * N + (size_t)(m0 + r) * N + gcol] = acc;
    }
#endif
}

// ---------------------------------------------------------------------------
// Q convert: fp32 row-major -> tiled SW128 bf16 hi/lo blocks.
// ---------------------------------------------------------------------------
__global__ void __launch_bounds__(256)
convert_q_kernel(const float* __restrict__ in,
                 __nv_bfloat16* __restrict__ hi, __nv_bfloat16* __restrict__ lo)
{
    const size_t i = (size_t)blockIdx.x * 256 + threadIdx.x;
    const size_t e0 = i * 8;
    const int b = (int)(e0 >> 21);              // TQ*HD = 2^21
    const int rem = (int)(e0 & ((1u << 21) - 1));
    const int q = rem >> 10;                     // HD = 1024
    const int d = rem & 1023;

    float4 v0 = *(const float4*)(in + e0);
    float4 v1 = *(const float4*)(in + e0 + 4);
    float v[8] = { v0.x, v0.y, v0.z, v0.w, v1.x, v1.y, v1.z, v1.w };
    __nv_bfloat16 h[8], l[8];
#pragma unroll
    for (int j = 0; j < 8; j++) split_bf16(v[j], h[j], l[j]);

    const size_t blk = ((size_t)b * 16 + (q >> 7)) * 16 + (d >> 6);
    const uint32_t off = sw128((uint32_t)((q & 127) * 128 + ((d & 63) >> 3) * 16));
    uint4 hv = { pack2(h[0], h[1]), pack2(h[2], h[3]), pack2(h[4], h[5]), pack2(h[6], h[7]) };
    uint4 lv = { pack2(l[0], l[1]), pack2(l[2], l[3]), pack2(l[4], l[5]), pack2(l[6], l[7]) };
    *(uint4*)((char*)hi + blk * 16384 + off) = hv;
    *(uint4*)((char*)lo + blk * 16384 + off) = lv;
}

// ---------------------------------------------------------------------------
// K convert: one read of K -> tiled K hi/lo (rows=t) AND tiled KT hi/lo (rows=d)
// ---------------------------------------------------------------------------
__global__ void __launch_bounds__(256)
k_convert_kernel(const float* __restrict__ Kin,
                 __nv_bfloat16* __restrict__ Khi, __nv_bfloat16* __restrict__ Klo,
                 __nv_bfloat16* __restrict__ KThi, __nv_bfloat16* __restrict__ KTlo)
{
    __shared__ float tile[32][33];
    const int b = blockIdx.z;
    const int t0 = blockIdx.x * 32, d0 = blockIdx.y * 32;
    const int tx = threadIdx.x & 31, ty = threadIdx.x >> 5;
    const float* src = Kin + (size_t)b * TK * HD;

#pragma unroll
    for (int r = 0; r < 4; r++) {
        const int t = t0 + ty + 8 * r;
        const int d = d0 + tx;
        const float v = src[(size_t)t * HD + d];
        tile[ty + 8 * r][tx] = v;
        __nv_bfloat16 h, l; split_bf16(v, h, l);
        const size_t blk = ((size_t)b * 16 + (t >> 7)) * 16 + (d >> 6);
        const uint32_t off = sw128((uint32_t)((t & 127) * 128 + (d & 63) * 2));
        *(__nv_bfloat16*)((char*)Khi + blk * 16384 + off) = h;
        *(__nv_bfloat16*)((char*)Klo + blk * 16384 + off) = l;
    }
    __syncthreads();
#pragma unroll
    for (int r = 0; r < 4; r++) {
        const int d = d0 + ty + 8 * r;
        const int t = t0 + tx;
        const float v = tile[tx][ty + 8 * r];
        __nv_bfloat16 h, l; split_bf16(v, h, l);
        const size_t blk = ((size_t)b * 8 + (d >> 7)) * 32 + (t >> 6);
        const uint32_t off = sw128((uint32_t)((d & 127) * 128 + (t & 63) * 2));
        *(__nv_bfloat16*)((char*)KThi + blk * 16384 + off) = h;
        *(__nv_bfloat16*)((char*)KTlo + blk * 16384 + off) = l;
    }
}

// ---------------------------------------------------------------------------
// Row softmax over TK; fp32 in (row-major), bf16 hi/lo out (TILED blocks).
// ---------------------------------------------------------------------------
__global__ void __launch_bounds__(256)
softmax_kernel(const float* __restrict__ E,
               __nv_bfloat16* __restrict__ Phi, __nv_bfloat16* __restrict__ Plo)
{
    const size_t row = blockIdx.x;
    const float* e = E + row * (size_t)TK;
    const int tid = threadIdx.x;
    const int lane = tid & 31, warp = tid >> 5;
    __shared__ float red[32];

    float4 a = *(const float4*)(e + tid * 8);
    float4 c = *(const float4*)(e + tid * 8 + 4);
    float v[8] = { a.x, a.y, a.z, a.w, c.x, c.y, c.z, c.w };

    float m = -INFINITY;
#pragma unroll
    for (int i = 0; i < 8; i++) m = fmaxf(m, v[i]);
#pragma unroll
    for (int o = 16; o > 0; o >>= 1) m = fmaxf(m, __shfl_xor_sync(0xffffffffu, m, o));
    if (lane == 0) red[warp] = m;
    __syncthreads();
    if (warp == 0) {
        float t = red[lane & 7];
#pragma unroll
        for (int o = 4; o > 0; o >>= 1) t = fmaxf(t, __shfl_xor_sync(0xffffffffu, t, o));
        red[lane] = t;
    }
    __syncthreads();
    m = red[0];

    float s = 0.0f;
#pragma unroll
    for (int i = 0; i < 8; i++) { v[i] = __expf(v[i] - m); s += v[i]; }
#pragma unroll
    for (int o = 16; o > 0; o >>= 1) s += __shfl_xor_sync(0xffffffffu, s, o);
    __syncthreads();
    if (lane == 0) red[warp] = s;
    __syncthreads();
    if (warp == 0) {
        float t = red[lane & 7];
#pragma unroll
        for (int o = 4; o > 0; o >>= 1) t += __shfl_xor_sync(0xffffffffu, t, o);
        red[lane] = t;
    }
    __syncthreads();
    const float inv = 1.0f / red[0];

    __nv_bfloat16 h[8], l[8];
#pragma unroll
    for (int i = 0; i < 8; i++) split_bf16(v[i] * inv, h[i], l[i]);

    const int b = (int)(row >> 11);             // TQ = 2048
    const int q = (int)(row & 2047);
    const size_t blk = ((size_t)b * 16 + (q >> 7)) * 32 + (tid >> 3);   // nch=32
    const uint32_t off = sw128((uint32_t)((q & 127) * 128 + (tid & 7) * 16));
    uint4 hv = { pack2(h[0], h[1]), pack2(h[2], h[3]), pack2(h[4], h[5]), pack2(h[6], h[7]) };
    uint4 lv = { pack2(l[0], l[1]), pack2(l[2], l[3]), pack2(l[4], l[5]), pack2(l[6], l[7]) };
    *(uint4*)((char*)Phi + blk * 16384 + off) = hv;
    *(uint4*)((char*)Plo + blk * 16384 + off) = lv;
}

// ---------------------------------------------------------------------------
extern "C" void kernel_launch(void* const* d_in, const int* in_sizes, int n_in,
                              void* d_out, int out_size)
{
    const float* Q  = (const float*)d_in[0];
    const float* Kt = (const float*)d_in[1];
    float* O = (float*)d_out;

    float *E; __nv_bfloat16 *Qhi, *Qlo, *Khi, *Klo, *KThi, *KTlo, *Phi, *Plo;
    cudaGetSymbolAddress((void**)&E,    g_E);
    cudaGetSymbolAddress((void**)&Qhi,  g_Qhi);
    cudaGetSymbolAddress((void**)&Qlo,  g_Qlo);
    cudaGetSymbolAddress((void**)&Khi,  g_Khi);
    cudaGetSymbolAddress((void**)&Klo,  g_Klo);
    cudaGetSymbolAddress((void**)&KThi, g_KThi);
    cudaGetSymbolAddress((void**)&KTlo, g_KTlo);
    cudaGetSymbolAddress((void**)&Phi,  g_Phi);
    cudaGetSymbolAddress((void**)&Plo,  g_Plo);

    cudaFuncSetAttribute(gemm_split_kernel,
                         cudaFuncAttributeMaxDynamicSharedMemorySize, GEMM_SMEM);

    // Q -> tiled hi/lo
    {
        size_t n8 = (size_t)BATCH * TQ * HD / 8;
        convert_q_kernel<<<(unsigned)(n8 / 256), 256>>>(Q, Qhi, Qlo);
    }
    // K -> tiled K hi/lo + tiled KT hi/lo
    {
        dim3 grid(TK / 32, HD / 32, BATCH);
        k_convert_kernel<<<grid, 256>>>(Kt, Khi, Klo, KThi, KTlo);
    }
    // GEMM1: E = Q K^T  (M=TQ, N=TK, Ktot=HD)
    {
        dim3 grid((TK / 256) * 2, TQ / 256, BATCH);
        gemm_split_kernel<<<grid, 256, GEMM_SMEM>>>(Qhi, Qlo, Khi, Klo, E, TQ, TK, HD);
    }
    softmax_kernel<<<BATCH * TQ, 256>>>(E, Phi, Plo);
    // GEMM2: O = P KT^T  (M=TQ, N=HD, Ktot=TK)
    {
        dim3 grid((HD / 256) * 2, TQ / 256, BATCH);
        gemm_split_kernel<<<grid, 256, GEMM_SMEM>>>(Phi, Plo, KThi, KTlo, O, TQ, HD, TK);
    }
    (void)in_sizes; (void)n_in; (void)out_size;
}